// round 14
// baseline (speedup 1.0000x reference)
#include <cuda_runtime.h>
#include <cuda_fp16.h>
#include <math.h>

#define Bn    4
#define HD    10
#define Hh    128
#define Ww    128
#define HWs   16384
#define NPIXs 65536          // Bn*HWs
#define NP    6
#define C1c   50
#define C2c   20
#define OUT_XP (NP*Bn*HD*HWs)   // 3932160
#define OUT_A  (NP*Bn*HWs)      // 393216

// ---------------- scratch (static device memory; no allocation) --------------
__device__ float g_om1[NP*Bn*27*HWs];
__device__ float g_om2[NP*Bn*27*HWs];
__device__ float g_y1 [NP*Bn*C2c*HWs];
__device__ float g_y2 [NP*Bn*HD*HWs];
__device__ float g_sum[1536];
__device__ float g_dscale[12*C2c], g_dshift[12*C2c];
__device__ float g_scale1[NP*C2c], g_shift1[NP*C2c];
__device__ float g_scale2[NP*HD],  g_shift2[NP*HD];

__device__ __constant__ int c_nbr0[6] = {1,0,1,2,3,0};
__device__ __constant__ int c_nbr1[6] = {5,2,3,4,5,4};

static __device__ __forceinline__ float2 h22f2(unsigned u){
    return __half22float2(*(__half2*)&u);
}

// ---------------------------------------------------------------------------
__global__ void zero_sums_kernel() {
    int i = blockIdx.x*256 + threadIdx.x;
    if (i < 1536) g_sum[i] = 0.f;
}

// ------------------ decomp stats: t = W1 @ concat(a,b), stats only ----------
__global__ __launch_bounds__(256) void decomp_t_kernel(
    const float* __restrict__ xf, const float* __restrict__ xh, const float* __restrict__ xp,
    const float* __restrict__ dfw1, const float* __restrict__ dhw1)
{
    int dp = blockIdx.y, dec = dp/6, part = dp%6;
    __shared__ __align__(16) float wt[400];   // [c*20+o]
    __shared__ float ssum[20], ssq[20];
    const float* W1 = (dec==0 ? dfw1 : dhw1) + part*400;
    int tid = threadIdx.x;
    for (int i = tid; i < 400; i += 256){
        int o = i/20, c = i%20;
        wt[c*20+o] = W1[i];
    }
    if (tid < 20) { ssum[tid]=0.f; ssq[tid]=0.f; }
    __syncthreads();

    int p = blockIdx.x*256 + tid;
    int b = p >> 14, pix = p & (HWs-1);
    const float* a   = (dec==0) ? (xf + b*HD*HWs)
                                : (xh + (((part<4?0:1)*Bn + b)*HD)*HWs);
    const float* xpi = xp + (part*Bn+b)*HD*HWs;

    float in[20];
#pragma unroll
    for (int c=0;c<10;c++) in[c]    = __ldg(a   + c*HWs + pix);
#pragma unroll
    for (int c=0;c<10;c++) in[10+c] = __ldg(xpi + c*HWs + pix);

    float out[20];
#pragma unroll
    for (int o=0;o<20;o++) out[o]=0.f;
#pragma unroll
    for (int c=0;c<20;c++){
        float vc = in[c];
        const float4* wp = (const float4*)&wt[c*20];
#pragma unroll
        for (int j=0;j<5;j++){
            float4 w4 = wp[j];
            out[4*j+0] += vc*w4.x; out[4*j+1] += vc*w4.y;
            out[4*j+2] += vc*w4.z; out[4*j+3] += vc*w4.w;
        }
    }

    for (int o=0;o<20;o++){
        float v = out[o], v2 = out[o]*out[o];
        for (int off=16; off; off>>=1){
            v  += __shfl_down_sync(0xffffffffu, v,  off);
            v2 += __shfl_down_sync(0xffffffffu, v2, off);
        }
        if ((tid&31)==0){ atomicAdd(&ssum[o], v); atomicAdd(&ssq[o], v2); }
    }
    __syncthreads();
    if (tid < 20){
        atomicAdd(&g_sum[dp*40 + tid*2],   ssum[tid]);
        atomicAdd(&g_sum[dp*40 + tid*2+1], ssq[tid]);
    }
}

__global__ void finalize_dec_kernel(const float* __restrict__ dfg, const float* __restrict__ dfb,
                                    const float* __restrict__ dhg, const float* __restrict__ dhb)
{
    int i = threadIdx.x;
    if (i < 240){
        int dp = i/20, ch = i%20, part = dp%6;
        float N = 65536.f;
        float mean = g_sum[dp*40+ch*2] / N;
        float var  = g_sum[dp*40+ch*2+1] / N - mean*mean;
        const float* g = (dp<6 ? dfg : dhg) + part*20;
        const float* b = (dp<6 ? dfb : dhb) + part*20;
        float sc = g[ch] * rsqrtf(var + 1e-5f);
        g_dscale[i] = sc;
        g_dshift[i] = b[ch] - mean*sc;
    }
}

// ------------- decomp out: recompute t, apply BN+leaky+W2+sigmoid -----------
__global__ __launch_bounds__(256) void decomp_out_kernel(
    const float* __restrict__ xf, const float* __restrict__ xh, const float* __restrict__ xp,
    const float* __restrict__ dfw1, const float* __restrict__ dhw1,
    const float* __restrict__ dfw2, const float* __restrict__ dfb2,
    const float* __restrict__ dhw2, const float* __restrict__ dhb2,
    float* __restrict__ out)
{
    int dp = blockIdx.y, dec = dp/6, part = dp%6;
    __shared__ __align__(16) float wt[400];   // [c*20+o]
    __shared__ float sw[20], sc[20], sh[20];
    const float* W1 = (dec==0 ? dfw1 : dhw1) + part*400;
    int tid = threadIdx.x;
    for (int i = tid; i < 400; i += 256){
        int o = i/20, c = i%20;
        wt[c*20+o] = W1[i];
    }
    if (tid < 20){
        sw[tid] = ((dec==0 ? dfw2 : dhw2) + part*20)[tid];
        sc[tid] = g_dscale[dp*20+tid];
        sh[tid] = g_dshift[dp*20+tid];
    }
    __syncthreads();

    int p = blockIdx.x*256 + tid;
    int b = p >> 14, pix = p & (HWs-1);
    const float* a   = (dec==0) ? (xf + b*HD*HWs)
                                : (xh + (((part<4?0:1)*Bn + b)*HD)*HWs);
    const float* xpi = xp + (part*Bn+b)*HD*HWs;

    float in[20];
#pragma unroll
    for (int c=0;c<10;c++) in[c]    = __ldg(a   + c*HWs + pix);
#pragma unroll
    for (int c=0;c<10;c++) in[10+c] = __ldg(xpi + c*HWs + pix);

    float out_t[20];
#pragma unroll
    for (int o=0;o<20;o++) out_t[o]=0.f;
#pragma unroll
    for (int c=0;c<20;c++){
        float vc = in[c];
        const float4* wp = (const float4*)&wt[c*20];
#pragma unroll
        for (int j=0;j<5;j++){
            float4 w4 = wp[j];
            out_t[4*j+0] += vc*w4.x; out_t[4*j+1] += vc*w4.y;
            out_t[4*j+2] += vc*w4.z; out_t[4*j+3] += vc*w4.w;
        }
    }
    float b2 = (dec==0 ? dfb2 : dhb2)[part];
    float s = b2;
#pragma unroll
    for (int c=0;c<20;c++){
        float t = out_t[c]*sc[c] + sh[c];
        t = (t >= 0.f) ? t : 0.01f*t;
        s += sw[c]*t;
    }
    out[OUT_XP + dec*OUT_A + part*NPIXs + p] = 1.f/(1.f+__expf(-s));
}

// --------- offset conv 1 (50ch -> 27ch), fp16 tile+weights ------------------
__global__ __launch_bounds__(384) void om1_kernel(
    const float* __restrict__ xf, const float* __restrict__ xh, const float* __restrict__ xp,
    const float* __restrict__ offw, const float* __restrict__ offb)
{
    int part = blockIdx.z, b = blockIdx.y;
    int ty0 = (blockIdx.x>>2)*16, tx0 = (blockIdx.x&3)*32;
    int tid = threadIdx.x;
    int og = tid>>7, lt = tid&127;
    int r = lt>>3, x0 = (lt&7)*4;

    __shared__ __align__(16) __half2 tileH[5][18][36];   // channel pair (2p,2p+1)
    __shared__ __align__(16) __half2 wtH[2160];          // [(c*9+t)*24 + og*8 + o2], o2 pairs outputs

    const float* srcs[5];
    srcs[0] = xp + (part*Bn+b)*HD*HWs;
    srcs[1] = xf + b*HD*HWs;
    srcs[2] = xh + (((part<4?0:1)*Bn+b)*HD)*HWs;
    srcs[3] = xp + (c_nbr0[part]*Bn+b)*HD*HWs;
    srcs[4] = xp + (c_nbr1[part]*Bn+b)*HD*HWs;
    const float* W = offw + part*27*C1c*9;

    float acc[9][4];
#pragma unroll
    for (int o=0;o<9;o++)
#pragma unroll
        for (int p=0;p<4;p++) acc[o][p] = 0.f;

    for (int chunk=0; chunk<5; chunk++){
        __syncthreads();
        for (int i=tid; i<1350; i+=384){
            int o2 = i%5, ogl = (i/5)%3, t = (i/15)%9, c = i/135;
            int oa = ogl*9 + o2*2;
            float wa = W[(oa*C1c + chunk*10 + c)*9 + t];
            float wb = (o2<4) ? W[((oa+1)*C1c + chunk*10 + c)*9 + t] : 0.f;
            wtH[(c*9+t)*24 + ogl*8 + o2] = __floats2half2_rn(wa, wb);
        }
        const float* sp = srcs[chunk];
        for (int i=tid; i<3060; i+=384){
            int p = i/612, rem = i%612, rr = rem/34, cc = rem%34;
            int gy = ty0-1+rr, gx = tx0-1+cc;
            float v0 = 0.f, v1 = 0.f;
            if (gy>=0 && gy<Hh && gx>=0 && gx<Ww){
                int gp = gy*Ww+gx;
                v0 = sp[(2*p  )*HWs + gp];
                v1 = sp[(2*p+1)*HWs + gp];
            }
            tileH[p][rr][cc] = __floats2half2_rn(v0, v1);
        }
        __syncthreads();
        for (int p=0;p<5;p++){
            unsigned inh[3][6];
#pragma unroll
            for (int dy=0;dy<3;dy++){
                const __half2* trow = &tileH[p][r+dy][x0];
                uint4 ua = *(const uint4*)trow;
                uint2 ub = *(const uint2*)(trow+4);
                inh[dy][0]=ua.x; inh[dy][1]=ua.y; inh[dy][2]=ua.z;
                inh[dy][3]=ua.w; inh[dy][4]=ub.x; inh[dy][5]=ub.y;
            }
#pragma unroll
            for (int t=0;t<9;t++){
                const __half2* wpa = &wtH[((2*p)*9+t)*24 + og*8];
                const __half2* wpb = &wtH[((2*p+1)*9+t)*24 + og*8];
                uint4 wua = *(const uint4*)wpa;
                unsigned wu8a = *(const unsigned*)(wpa+4);
                uint4 wub = *(const uint4*)wpb;
                unsigned wu8b = *(const unsigned*)(wpb+4);
                float2 a01=h22f2(wua.x), a23=h22f2(wua.y), a45=h22f2(wua.z), a67=h22f2(wua.w), a8=h22f2(wu8a);
                float2 b01=h22f2(wub.x), b23=h22f2(wub.y), b45=h22f2(wub.z), b67=h22f2(wub.w), b8=h22f2(wu8b);
                int ty = t/3, tx = t%3;
                float2 i0 = h22f2(inh[ty][tx+0]);
                float2 i1 = h22f2(inh[ty][tx+1]);
                float2 i2 = h22f2(inh[ty][tx+2]);
                float2 i3 = h22f2(inh[ty][tx+3]);
                float ivA[4] = {i0.x, i1.x, i2.x, i3.x};
                float ivB[4] = {i0.y, i1.y, i2.y, i3.y};
                float wA[9] = {a01.x,a01.y,a23.x,a23.y,a45.x,a45.y,a67.x,a67.y,a8.x};
                float wB[9] = {b01.x,b01.y,b23.x,b23.y,b45.x,b45.y,b67.x,b67.y,b8.x};
#pragma unroll
                for (int o=0;o<9;o++){
                    float wa = wA[o], wb = wB[o];
#pragma unroll
                    for (int q=0;q<4;q++)
                        acc[o][q] += ivA[q]*wa + ivB[q]*wb;
                }
            }
        }
    }
    float* omp = g_om1 + (part*Bn+b)*27*HWs;
    int y = ty0+r;
#pragma unroll
    for (int o=0;o<9;o++){
        int oo = og*9+o;
        float bv = __ldg(offb + part*27 + oo);
#pragma unroll
        for (int p=0;p<4;p++)
            omp[oo*HWs + y*Ww + tx0+x0+p] = acc[o][p] + bv;
    }
}

// --------- offset conv 2 (20ch(t1) -> 27ch), fp16 tile+weights --------------
__global__ __launch_bounds__(384) void om2_kernel(
    const float* __restrict__ offw, const float* __restrict__ offb)
{
    int part = blockIdx.z, b = blockIdx.y;
    int ty0 = (blockIdx.x>>2)*16, tx0 = (blockIdx.x&3)*32;
    int tid = threadIdx.x;
    int og = tid>>7, lt = tid&127;
    int r = lt>>3, x0 = (lt&7)*4;

    __shared__ __align__(16) __half2 tileH[5][18][36];
    __shared__ __align__(16) __half2 wtH[2160];
    __shared__ float ssc[20], ssh[20];
    if (tid < 20){ ssc[tid] = g_scale1[part*20+tid]; ssh[tid] = g_shift1[part*20+tid]; }

    const float* sp0 = g_y1 + (part*Bn+b)*C2c*HWs;
    const float* W = offw + part*27*C2c*9;

    float acc[9][4];
#pragma unroll
    for (int o=0;o<9;o++)
#pragma unroll
        for (int p=0;p<4;p++) acc[o][p] = 0.f;

    for (int chunk=0; chunk<2; chunk++){
        __syncthreads();
        for (int i=tid; i<1350; i+=384){
            int o2 = i%5, ogl = (i/5)%3, t = (i/15)%9, c = i/135;
            int oa = ogl*9 + o2*2;
            float wa = W[(oa*C2c + chunk*10 + c)*9 + t];
            float wb = (o2<4) ? W[((oa+1)*C2c + chunk*10 + c)*9 + t] : 0.f;
            wtH[(c*9+t)*24 + ogl*8 + o2] = __floats2half2_rn(wa, wb);
        }
        for (int i=tid; i<3060; i+=384){
            int p = i/612, rem = i%612, rr = rem/34, cc = rem%34;
            int gy = ty0-1+rr, gx = tx0-1+cc;
            float v0 = 0.f, v1 = 0.f;
            if (gy>=0 && gy<Hh && gx>=0 && gx<Ww){
                int gp = gy*Ww+gx;
                int gc0 = chunk*10 + 2*p;
                v0 = fmaxf(sp0[gc0*HWs + gp]*ssc[gc0] + ssh[gc0], 0.f);
                v1 = fmaxf(sp0[(gc0+1)*HWs + gp]*ssc[gc0+1] + ssh[gc0+1], 0.f);
            }
            tileH[p][rr][cc] = __floats2half2_rn(v0, v1);
        }
        __syncthreads();
        for (int p=0;p<5;p++){
            unsigned inh[3][6];
#pragma unroll
            for (int dy=0;dy<3;dy++){
                const __half2* trow = &tileH[p][r+dy][x0];
                uint4 ua = *(const uint4*)trow;
                uint2 ub = *(const uint2*)(trow+4);
                inh[dy][0]=ua.x; inh[dy][1]=ua.y; inh[dy][2]=ua.z;
                inh[dy][3]=ua.w; inh[dy][4]=ub.x; inh[dy][5]=ub.y;
            }
#pragma unroll
            for (int t=0;t<9;t++){
                const __half2* wpa = &wtH[((2*p)*9+t)*24 + og*8];
                const __half2* wpb = &wtH[((2*p+1)*9+t)*24 + og*8];
                uint4 wua = *(const uint4*)wpa;
                unsigned wu8a = *(const unsigned*)(wpa+4);
                uint4 wub = *(const uint4*)wpb;
                unsigned wu8b = *(const unsigned*)(wpb+4);
                float2 a01=h22f2(wua.x), a23=h22f2(wua.y), a45=h22f2(wua.z), a67=h22f2(wua.w), a8=h22f2(wu8a);
                float2 b01=h22f2(wub.x), b23=h22f2(wub.y), b45=h22f2(wub.z), b67=h22f2(wub.w), b8=h22f2(wu8b);
                int ty = t/3, tx = t%3;
                float2 i0 = h22f2(inh[ty][tx+0]);
                float2 i1 = h22f2(inh[ty][tx+1]);
                float2 i2 = h22f2(inh[ty][tx+2]);
                float2 i3 = h22f2(inh[ty][tx+3]);
                float ivA[4] = {i0.x, i1.x, i2.x, i3.x};
                float ivB[4] = {i0.y, i1.y, i2.y, i3.y};
                float wA[9] = {a01.x,a01.y,a23.x,a23.y,a45.x,a45.y,a67.x,a67.y,a8.x};
                float wB[9] = {b01.x,b01.y,b23.x,b23.y,b45.x,b45.y,b67.x,b67.y,b8.x};
#pragma unroll
                for (int o=0;o<9;o++){
                    float wa = wA[o], wb = wB[o];
#pragma unroll
                    for (int q=0;q<4;q++)
                        acc[o][q] += ivA[q]*wa + ivB[q]*wb;
                }
            }
        }
    }
    float* omp = g_om2 + (part*Bn+b)*27*HWs;
    int y = ty0+r;
#pragma unroll
    for (int o=0;o<9;o++){
        int oo = og*9+o;
        float bv = __ldg(offb + part*27 + oo);
#pragma unroll
        for (int p=0;p<4;p++)
            omp[oo*HWs + y*Ww + tx0+x0+p] = acc[o][p] + bv;
    }
}

// ------- deform conv 1 (50ch -> 20ch), fp16 tile, 2 px/thread ---------------
__global__ __launch_bounds__(256) void deform1_kernel(
    const float* __restrict__ xf, const float* __restrict__ xh, const float* __restrict__ xp,
    const float* __restrict__ w1)
{
    int part = blockIdx.z, b = blockIdx.y;
    int ty0 = (blockIdx.x>>3)*32, tx0 = (blockIdx.x&7)*16;
    int tid = threadIdx.x;
    int ly = tid>>4, lx = tid&15;
    int sy0 = ty0-3, sx0 = tx0-3;   // halo 38 rows x 22 cols

    __shared__ __align__(16) float wt[1800];        // [(c*9+k)*20+o], 10ch chunk
    __shared__ __align__(16) __half2 tileH[5][836]; // [cpair][pos 38x22]
    __shared__ float ssum[20], ssq[20];

    const float* src0 = xp + (part*Bn+b)*HD*HWs;
    const float* src1 = xf + b*HD*HWs;
    const float* src2 = xh + (((part<4?0:1)*Bn+b)*HD)*HWs;
    const float* src3 = xp + (c_nbr0[part]*Bn+b)*HD*HWs;
    const float* src4 = xp + (c_nbr1[part]*Bn+b)*HD*HWs;
    const float* Wm = w1 + part*9000;
    if (tid < 20){ ssum[tid]=0.f; ssq[tid]=0.f; }

    int pix0 = (ty0+ly)*Ww + tx0+lx;
    int pix1 = pix0 + 16*Ww;

    float tw[2][9][4]; int tiy[2][9], tix[2][9]; unsigned inmask[2] = {0u,0u};
    for (int j=0;j<2;j++){
        int yj = ty0+ly + j*16, xj = tx0+lx;
        const float* omp = g_om1 + (part*Bn+b)*27*HWs + (j ? pix1 : pix0);
        for (int k=0;k<9;k++){
            float dy = omp[(2*k)*HWs], dx = omp[(2*k+1)*HWs];
            float m  = 1.f/(1.f+__expf(-omp[(18+k)*HWs]));
            float py = (float)(yj + k/3 - 1) + dy;
            float px = (float)(xj + (k%3) - 1) + dx;
            float fy = floorf(py), fx = floorf(px);
            float wy = py-fy, wx = px-fx;
            int iy = (int)fy, ix = (int)fx;
            tw[j][k][0] = (1.f-wy)*(1.f-wx)*m;
            tw[j][k][1] = (1.f-wy)*wx*m;
            tw[j][k][2] = wy*(1.f-wx)*m;
            tw[j][k][3] = wy*wx*m;
            tiy[j][k]=iy; tix[j][k]=ix;
            if (iy>=sy0 && iy<=sy0+36 && ix>=sx0 && ix<=sx0+20) inmask[j] |= (1u<<k);
        }
    }
    float acc[2][20];
#pragma unroll
    for (int j=0;j<2;j++)
#pragma unroll
        for (int o=0;o<20;o++) acc[j][o]=0.f;

    for (int chunk=0; chunk<5; chunk++){
        const float* spb;
        switch (chunk){
            case 0: spb = src0; break;
            case 1: spb = src1; break;
            case 2: spb = src2; break;
            case 3: spb = src3; break;
            default: spb = src4; break;
        }
        __syncthreads();
        for (int i=tid; i<1800; i+=256){
            int o = i%20, k = (i/20)%9, c = i/180;
            wt[(c*9+k)*20+o] = Wm[(o*50 + chunk*10 + c)*9 + k];
        }
        for (int i=tid; i<4180; i+=256){
            int p = i/836, rem = i%836;
            int gy = sy0+rem/22, gx = sx0+rem%22;
            float v0 = 0.f, v1 = 0.f;
            if (gy>=0 && gy<Hh && gx>=0 && gx<Ww){
                int gp = gy*Ww+gx;
                v0 = spb[(2*p  )*HWs + gp];
                v1 = spb[(2*p+1)*HWs + gp];
            }
            tileH[p][rem] = __floats2half2_rn(v0, v1);
        }
        __syncthreads();
        for (int k=0;k<9;k++){
            float v[2][10];
#pragma unroll
            for (int j=0;j<2;j++){
                float w00=tw[j][k][0], w01=tw[j][k][1], w10=tw[j][k][2], w11=tw[j][k][3];
                int iy=tiy[j][k], ix=tix[j][k];
                if (inmask[j] & (1u<<k)){
                    int base = (iy-sy0)*22 + (ix-sx0);
#pragma unroll
                    for (int p=0;p<5;p++){
                        const __half2* tp = tileH[p];
                        float2 fa = __half22float2(tp[base]);
                        float2 fb = __half22float2(tp[base+1]);
                        float2 fc = __half22float2(tp[base+22]);
                        float2 fd = __half22float2(tp[base+23]);
                        v[j][2*p+0] = w00*fa.x + w01*fb.x + w10*fc.x + w11*fd.x;
                        v[j][2*p+1] = w00*fa.y + w01*fb.y + w10*fc.y + w11*fd.y;
                    }
                } else {
                    bool vy0 = (iy>=0)&&(iy<Hh),   vy1 = (iy+1>=0)&&(iy+1<Hh);
                    bool vx0 = (ix>=0)&&(ix<Ww),   vx1 = (ix+1>=0)&&(ix+1<Ww);
                    int i00 = iy*Ww+ix;
#pragma unroll
                    for (int c=0;c<10;c++){
                        const float* sp = spb + c*HWs;
                        float v00 = (vy0&&vx0)? sp[i00]      : 0.f;
                        float v01 = (vy0&&vx1)? sp[i00+1]    : 0.f;
                        float v10 = (vy1&&vx0)? sp[i00+Ww]   : 0.f;
                        float v11 = (vy1&&vx1)? sp[i00+Ww+1] : 0.f;
                        v[j][c] = w00*v00 + w01*v01 + w10*v10 + w11*v11;
                    }
                }
            }
#pragma unroll
            for (int c=0;c<10;c++){
                float v0 = v[0][c], v1 = v[1][c];
                const float4* wp = (const float4*)&wt[(c*9+k)*20];
#pragma unroll
                for (int q=0;q<5;q++){
                    float4 w4 = wp[q];
                    acc[0][4*q+0] += v0*w4.x; acc[0][4*q+1] += v0*w4.y;
                    acc[0][4*q+2] += v0*w4.z; acc[0][4*q+3] += v0*w4.w;
                    acc[1][4*q+0] += v1*w4.x; acc[1][4*q+1] += v1*w4.y;
                    acc[1][4*q+2] += v1*w4.z; acc[1][4*q+3] += v1*w4.w;
                }
            }
        }
    }
    float* yb = g_y1 + (part*Bn+b)*C2c*HWs;
#pragma unroll
    for (int o=0;o<20;o++){
        yb[o*HWs + pix0] = acc[0][o];
        yb[o*HWs + pix1] = acc[1][o];
    }
    for (int o=0;o<20;o++){
        float v  = acc[0][o]+acc[1][o];
        float v2 = acc[0][o]*acc[0][o]+acc[1][o]*acc[1][o];
        for (int off=16; off; off>>=1){
            v  += __shfl_down_sync(0xffffffffu, v,  off);
            v2 += __shfl_down_sync(0xffffffffu, v2, off);
        }
        if ((tid&31)==0){ atomicAdd(&ssum[o], v); atomicAdd(&ssq[o], v2); }
    }
    __syncthreads();
    if (tid < 20){
        atomicAdd(&g_sum[512 + part*40 + tid*2],   ssum[tid]);
        atomicAdd(&g_sum[512 + part*40 + tid*2+1], ssq[tid]);
    }
}

__global__ void finalize1_kernel(const float* __restrict__ g1, const float* __restrict__ b1){
    int i = threadIdx.x;
    if (i < 120){
        int part = i/20, ch = i%20;
        float mean = g_sum[512+part*40+ch*2] / 65536.f;
        float var  = g_sum[512+part*40+ch*2+1] / 65536.f - mean*mean;
        float sc = g1[part*20+ch]*rsqrtf(var + 1e-5f);
        g_scale1[i] = sc;
        g_shift1[i] = b1[part*20+ch] - mean*sc;
    }
}

// ------- deform conv 2 (20ch -> 10ch), fp16 tile, 2 px/thread ---------------
__global__ __launch_bounds__(256) void deform2_kernel(const float* __restrict__ w2)
{
    int part = blockIdx.z, b = blockIdx.y;
    int ty0 = (blockIdx.x>>3)*32, tx0 = (blockIdx.x&7)*16;
    int tid = threadIdx.x;
    int ly = tid>>4, lx = tid&15;
    int sy0 = ty0-3, sx0 = tx0-3;

    __shared__ __align__(16) float wt[1080];        // [(c*9+k)*12+o], 10ch chunk
    __shared__ __align__(16) __half2 tileH[5][836];
    __shared__ float ssc[20], ssh[20];
    __shared__ float ssum[10], ssq[10];

    const float* t1p = g_y1 + (part*Bn+b)*C2c*HWs;
    const float* Wm = w2 + part*1800;
    if (tid < 20){ ssc[tid] = g_scale1[part*20+tid]; ssh[tid] = g_shift1[part*20+tid]; }
    if (tid < 10){ ssum[tid]=0.f; ssq[tid]=0.f; }
    __syncthreads();

    int pix0 = (ty0+ly)*Ww + tx0+lx;
    int pix1 = pix0 + 16*Ww;

    float tw[2][9][4]; int tiy[2][9], tix[2][9]; unsigned inmask[2] = {0u,0u};
    for (int j=0;j<2;j++){
        int yj = ty0+ly + j*16, xj = tx0+lx;
        const float* omp = g_om2 + (part*Bn+b)*27*HWs + (j ? pix1 : pix0);
        for (int k=0;k<9;k++){
            float dy = omp[(2*k)*HWs], dx = omp[(2*k+1)*HWs];
            float m  = 1.f/(1.f+__expf(-omp[(18+k)*HWs]));
            float py = (float)(yj + k/3 - 1) + dy;
            float px = (float)(xj + (k%3) - 1) + dx;
            float fy = floorf(py), fx = floorf(px);
            float wy = py-fy, wx = px-fx;
            int iy = (int)fy, ix = (int)fx;
            tw[j][k][0] = (1.f-wy)*(1.f-wx)*m;
            tw[j][k][1] = (1.f-wy)*wx*m;
            tw[j][k][2] = wy*(1.f-wx)*m;
            tw[j][k][3] = wy*wx*m;
            tiy[j][k]=iy; tix[j][k]=ix;
            if (iy>=sy0 && iy<=sy0+36 && ix>=sx0 && ix<=sx0+20) inmask[j] |= (1u<<k);
        }
    }
    float acc[2][10];
#pragma unroll
    for (int j=0;j<2;j++)
#pragma unroll
        for (int o=0;o<10;o++) acc[j][o]=0.f;

    for (int chunk=0; chunk<2; chunk++){
        __syncthreads();
        for (int i=tid; i<900; i+=256){
            int o = i%10, k = (i/10)%9, c = i/90;
            wt[(c*9+k)*12+o] = Wm[(o*20 + chunk*10 + c)*9 + k];
        }
        for (int i=tid; i<4180; i+=256){
            int p = i/836, rem = i%836;
            int gy = sy0+rem/22, gx = sx0+rem%22;
            float v0 = 0.f, v1 = 0.f;
            if (gy>=0 && gy<Hh && gx>=0 && gx<Ww){
                int gp = gy*Ww+gx;
                int gc0 = chunk*10 + 2*p;
                v0 = fmaxf(t1p[gc0*HWs + gp]*ssc[gc0] + ssh[gc0], 0.f);
                v1 = fmaxf(t1p[(gc0+1)*HWs + gp]*ssc[gc0+1] + ssh[gc0+1], 0.f);
            }
            tileH[p][rem] = __floats2half2_rn(v0, v1);
        }
        __syncthreads();
        for (int k=0;k<9;k++){
            float v[2][10];
#pragma unroll
            for (int j=0;j<2;j++){
                float w00=tw[j][k][0], w01=tw[j][k][1], w10=tw[j][k][2], w11=tw[j][k][3];
                int iy=tiy[j][k], ix=tix[j][k];
                if (inmask[j] & (1u<<k)){
                    int base = (iy-sy0)*22 + (ix-sx0);
#pragma unroll
                    for (int p=0;p<5;p++){
                        const __half2* tp = tileH[p];
                        float2 fa = __half22float2(tp[base]);
                        float2 fb = __half22float2(tp[base+1]);
                        float2 fc = __half22float2(tp[base+22]);
                        float2 fd = __half22float2(tp[base+23]);
                        v[j][2*p+0] = w00*fa.x + w01*fb.x + w10*fc.x + w11*fd.x;
                        v[j][2*p+1] = w00*fa.y + w01*fb.y + w10*fc.y + w11*fd.y;
                    }
                } else {
                    bool vy0 = (iy>=0)&&(iy<Hh),   vy1 = (iy+1>=0)&&(iy+1<Hh);
                    bool vx0 = (ix>=0)&&(ix<Ww),   vx1 = (ix+1>=0)&&(ix+1<Ww);
                    int i00 = iy*Ww+ix;
#pragma unroll
                    for (int c=0;c<10;c++){
                        int gc = chunk*10+c;
                        const float* sp = t1p + gc*HWs;
                        float sc2 = ssc[gc], sh2 = ssh[gc];
                        float v00 = (vy0&&vx0)? fmaxf(sp[i00]     *sc2+sh2,0.f) : 0.f;
                        float v01 = (vy0&&vx1)? fmaxf(sp[i00+1]   *sc2+sh2,0.f) : 0.f;
                        float v10 = (vy1&&vx0)? fmaxf(sp[i00+Ww]  *sc2+sh2,0.f) : 0.f;
                        float v11 = (vy1&&vx1)? fmaxf(sp[i00+Ww+1]*sc2+sh2,0.f) : 0.f;
                        v[j][c] = w00*v00 + w01*v01 + w10*v10 + w11*v11;
                    }
                }
            }
#pragma unroll
            for (int c=0;c<10;c++){
                float v0 = v[0][c], v1 = v[1][c];
                const float* wp = &wt[(c*9+k)*12];
                float4 wa = *(const float4*)wp;
                float4 wb = *(const float4*)(wp+4);
                float2 wc = *(const float2*)(wp+8);
                acc[0][0]+=v0*wa.x; acc[0][1]+=v0*wa.y; acc[0][2]+=v0*wa.z; acc[0][3]+=v0*wa.w;
                acc[0][4]+=v0*wb.x; acc[0][5]+=v0*wb.y; acc[0][6]+=v0*wb.z; acc[0][7]+=v0*wb.w;
                acc[0][8]+=v0*wc.x; acc[0][9]+=v0*wc.y;
                acc[1][0]+=v1*wa.x; acc[1][1]+=v1*wa.y; acc[1][2]+=v1*wa.z; acc[1][3]+=v1*wa.w;
                acc[1][4]+=v1*wb.x; acc[1][5]+=v1*wb.y; acc[1][6]+=v1*wb.z; acc[1][7]+=v1*wb.w;
                acc[1][8]+=v1*wc.x; acc[1][9]+=v1*wc.y;
            }
        }
    }
    float* yb = g_y2 + (part*Bn+b)*HD*HWs;
#pragma unroll
    for (int o=0;o<10;o++){
        yb[o*HWs + pix0] = acc[0][o];
        yb[o*HWs + pix1] = acc[1][o];
    }
    for (int o=0;o<10;o++){
        float v  = acc[0][o]+acc[1][o];
        float v2 = acc[0][o]*acc[0][o]+acc[1][o]*acc[1][o];
        for (int off=16; off; off>>=1){
            v  += __shfl_down_sync(0xffffffffu, v,  off);
            v2 += __shfl_down_sync(0xffffffffu, v2, off);
        }
        if ((tid&31)==0){ atomicAdd(&ssum[o], v); atomicAdd(&ssq[o], v2); }
    }
    __syncthreads();
    if (tid < 10){
        atomicAdd(&g_sum[1024 + part*20 + tid*2],   ssum[tid]);
        atomicAdd(&g_sum[1024 + part*20 + tid*2+1], ssq[tid]);
    }
}

__global__ void finalize2_kernel(const float* __restrict__ g2, const float* __restrict__ b2){
    int i = threadIdx.x;
    if (i < 60){
        int part = i/10, ch = i%10;
        float mean = g_sum[1024+part*20+ch*2] / 65536.f;
        float var  = g_sum[1024+part*20+ch*2+1] / 65536.f - mean*mean;
        float sc = g2[part*10+ch]*rsqrtf(var + 1e-5f);
        g_scale2[i] = sc;
        g_shift2[i] = b2[part*10+ch] - mean*sc;
    }
}

__global__ void final_kernel(const float* __restrict__ xp, const float* __restrict__ gamma,
                             float* __restrict__ out)
{
    int idx4 = blockIdx.x*256 + threadIdx.x;
    if (idx4 >= OUT_XP/4) return;
    int idx = idx4*4;
    int ch = (idx >> 14) % HD;
    int part = idx / (Bn*HD*HWs);
    float sc = g_scale2[part*HD+ch], sh = g_shift2[part*HD+ch];
    float gm = __ldg(gamma + part);
    float4 yv = *(const float4*)&g_y2[idx];
    float4 xv = *(const float4*)&xp[idx];
    float4 r;
    r.x = fmaxf(gm*xv.x + fmaxf(yv.x*sc+sh, 0.f), 0.f);
    r.y = fmaxf(gm*xv.y + fmaxf(yv.y*sc+sh, 0.f), 0.f);
    r.z = fmaxf(gm*xv.z + fmaxf(yv.z*sc+sh, 0.f), 0.f);
    r.w = fmaxf(gm*xv.w + fmaxf(yv.w*sc+sh, 0.f), 0.f);
    *(float4*)&out[idx] = r;
}

// ---------------------------------------------------------------------------
extern "C" void kernel_launch(void* const* d_in, const int* in_sizes, int n_in,
                              void* d_out, int out_size)
{
    const float* xf   = (const float*)d_in[0];
    const float* xh   = (const float*)d_in[1];
    const float* xp   = (const float*)d_in[2];
    const float* dfw1 = (const float*)d_in[3];
    const float* dfg1 = (const float*)d_in[4];
    const float* dfb1 = (const float*)d_in[5];
    const float* dfw2 = (const float*)d_in[6];
    const float* dfb2 = (const float*)d_in[7];
    const float* dhw1 = (const float*)d_in[8];
    const float* dhg1 = (const float*)d_in[9];
    const float* dhb1 = (const float*)d_in[10];
    const float* dhw2 = (const float*)d_in[11];
    const float* dhb2 = (const float*)d_in[12];
    const float* off1w= (const float*)d_in[13];
    const float* off1b= (const float*)d_in[14];
    const float* w1   = (const float*)d_in[15];
    const float* g1   = (const float*)d_in[16];
    const float* b1   = (const float*)d_in[17];
    const float* off2w= (const float*)d_in[18];
    const float* off2b= (const float*)d_in[19];
    const float* w2   = (const float*)d_in[20];
    const float* g2   = (const float*)d_in[21];
    const float* b2   = (const float*)d_in[22];
    const float* gamma= (const float*)d_in[23];
    float* out = (float*)d_out;

    zero_sums_kernel<<<6, 256>>>();
    decomp_t_kernel<<<dim3(256,12), 256>>>(xf, xh, xp, dfw1, dhw1);
    om1_kernel<<<dim3(32,4,6), 384>>>(xf, xh, xp, off1w, off1b);
    deform1_kernel<<<dim3(32,4,6), 256>>>(xf, xh, xp, w1);
    finalize_dec_kernel<<<1, 256>>>(dfg1, dfb1, dhg1, dhb1);
    decomp_out_kernel<<<dim3(256,12), 256>>>(xf, xh, xp, dfw1, dhw1,
                                             dfw2, dfb2, dhw2, dhb2, out);
    finalize1_kernel<<<1, 128>>>(g1, b1);
    om2_kernel<<<dim3(32,4,6), 384>>>(off2w, off2b);
    deform2_kernel<<<dim3(32,4,6), 256>>>(w2);
    finalize2_kernel<<<1, 64>>>(g2, b2);
    final_kernel<<<(OUT_XP/4+255)/256, 256>>>(xp, gamma, out);
}

// round 15
// speedup vs baseline: 1.1382x; 1.1382x over previous
#include <cuda_runtime.h>
#include <cuda_fp16.h>
#include <math.h>

#define Bn    4
#define HD    10
#define Hh    128
#define Ww    128
#define HWs   16384
#define NPIXs 65536          // Bn*HWs
#define NP    6
#define C1c   50
#define C2c   20
#define OUT_XP (NP*Bn*HD*HWs)   // 3932160
#define OUT_A  (NP*Bn*HWs)      // 393216

// ---------------- scratch (static device memory; no allocation) --------------
__device__ float g_om1[NP*Bn*27*HWs];
__device__ float g_om2[NP*Bn*27*HWs];
__device__ float g_y1 [NP*Bn*C2c*HWs];
__device__ float g_y2 [NP*Bn*HD*HWs];
__device__ float g_sum[1536];
__device__ float g_dscale[12*C2c], g_dshift[12*C2c];
__device__ float g_scale1[NP*C2c], g_shift1[NP*C2c];
__device__ float g_scale2[NP*HD],  g_shift2[NP*HD];

__device__ __constant__ int c_nbr0[6] = {1,0,1,2,3,0};
__device__ __constant__ int c_nbr1[6] = {5,2,3,4,5,4};

// ---------------------------------------------------------------------------
__global__ void zero_sums_kernel() {
    int i = blockIdx.x*256 + threadIdx.x;
    if (i < 1536) g_sum[i] = 0.f;
}

// ===== fused kernel 1: om1 (blocks x<32) + decomp_t stats (blocks x>=32) ====
__global__ __launch_bounds__(384) void fused1_kernel(
    const float* __restrict__ xf, const float* __restrict__ xh, const float* __restrict__ xp,
    const float* __restrict__ offw, const float* __restrict__ offb,
    const float* __restrict__ dfw1, const float* __restrict__ dhw1)
{
    __shared__ __align__(16) float tileS[10][18][36];
    __shared__ __align__(16) float wtc[3240];     // om weights [(c*9+t)*36 + og*12 + o]
    __shared__ __align__(16) float wtd[400];      // decomp W1 [c*20+o]
    __shared__ float ssum[20], ssq[20];

    int tid = threadIdx.x;
    int part = blockIdx.z, b = blockIdx.y;

    if (blockIdx.x < 32){
        // ---------------- om1: offset conv 1 (50ch -> 27ch) -----------------
        int xblk = blockIdx.x;
        int ty0 = (xblk>>2)*16, tx0 = (xblk&3)*32;
        int og = tid>>7, lt = tid&127;
        int r = lt>>3, x0 = (lt&7)*4;

        const float* srcs[5];
        srcs[0] = xp + (part*Bn+b)*HD*HWs;
        srcs[1] = xf + b*HD*HWs;
        srcs[2] = xh + (((part<4?0:1)*Bn+b)*HD)*HWs;
        srcs[3] = xp + (c_nbr0[part]*Bn+b)*HD*HWs;
        srcs[4] = xp + (c_nbr1[part]*Bn+b)*HD*HWs;
        const float* W = offw + part*27*C1c*9;

        float acc[9][4];
#pragma unroll
        for (int o=0;o<9;o++)
#pragma unroll
            for (int p=0;p<4;p++) acc[o][p] = 0.f;

        for (int chunk=0; chunk<5; chunk++){
            __syncthreads();
            for (int i=tid; i<2430; i+=384){
                int t = i%9, c = (i/9)%10, o27 = i/90;
                int ogl = o27/9, o = o27%9;
                wtc[(c*9+t)*36 + ogl*12 + o] = W[(o27*C1c + chunk*10 + c)*9 + t];
            }
            const float* sp = srcs[chunk];
            for (int i=tid; i<6120; i+=384){
                int c = i/612, rem = i%612, rr = rem/34, cc = rem%34;
                int gy = ty0-1+rr, gx = tx0-1+cc;
                float v = 0.f;
                if (gy>=0 && gy<Hh && gx>=0 && gx<Ww) v = sp[c*HWs + gy*Ww + gx];
                tileS[c][rr][cc] = v;
            }
            __syncthreads();
#pragma unroll 2
            for (int c=0;c<10;c++){
                float in[3][6];
#pragma unroll
                for (int dy=0;dy<3;dy++){
                    const float* trow = &tileS[c][r+dy][x0];
                    float4 a4 = *(const float4*)trow;
                    float2 b2 = *(const float2*)(trow+4);
                    in[dy][0]=a4.x; in[dy][1]=a4.y; in[dy][2]=a4.z; in[dy][3]=a4.w;
                    in[dy][4]=b2.x; in[dy][5]=b2.y;
                }
#pragma unroll
                for (int t=0;t<9;t++){
                    const float* wp = &wtc[(c*9+t)*36 + og*12];
                    float4 wa = *(const float4*)wp;
                    float4 wb = *(const float4*)(wp+4);
                    float  w8 = wp[8];
                    float iv0 = in[t/3][t%3+0], iv1 = in[t/3][t%3+1];
                    float iv2 = in[t/3][t%3+2], iv3 = in[t/3][t%3+3];
                    acc[0][0]+=iv0*wa.x; acc[0][1]+=iv1*wa.x; acc[0][2]+=iv2*wa.x; acc[0][3]+=iv3*wa.x;
                    acc[1][0]+=iv0*wa.y; acc[1][1]+=iv1*wa.y; acc[1][2]+=iv2*wa.y; acc[1][3]+=iv3*wa.y;
                    acc[2][0]+=iv0*wa.z; acc[2][1]+=iv1*wa.z; acc[2][2]+=iv2*wa.z; acc[2][3]+=iv3*wa.z;
                    acc[3][0]+=iv0*wa.w; acc[3][1]+=iv1*wa.w; acc[3][2]+=iv2*wa.w; acc[3][3]+=iv3*wa.w;
                    acc[4][0]+=iv0*wb.x; acc[4][1]+=iv1*wb.x; acc[4][2]+=iv2*wb.x; acc[4][3]+=iv3*wb.x;
                    acc[5][0]+=iv0*wb.y; acc[5][1]+=iv1*wb.y; acc[5][2]+=iv2*wb.y; acc[5][3]+=iv3*wb.y;
                    acc[6][0]+=iv0*wb.z; acc[6][1]+=iv1*wb.z; acc[6][2]+=iv2*wb.z; acc[6][3]+=iv3*wb.z;
                    acc[7][0]+=iv0*wb.w; acc[7][1]+=iv1*wb.w; acc[7][2]+=iv2*wb.w; acc[7][3]+=iv3*wb.w;
                    acc[8][0]+=iv0*w8;   acc[8][1]+=iv1*w8;   acc[8][2]+=iv2*w8;   acc[8][3]+=iv3*w8;
                }
            }
        }
        float* omp = g_om1 + (part*Bn+b)*27*HWs;
        int y = ty0+r;
#pragma unroll
        for (int o=0;o<9;o++){
            int oo = og*9+o;
            float bv = __ldg(offb + part*27 + oo);
#pragma unroll
            for (int p=0;p<4;p++)
                omp[oo*HWs + y*Ww + tx0+x0+p] = acc[o][p] + bv;
        }
    } else {
        // ---------------- decomp_t stats (12 dp x 65536 px) -----------------
        int bi = (blockIdx.x-32) + 86*(blockIdx.z*4 + blockIdx.y);
        if (bi >= 2052) return;
        int dp = bi/171, dec = dp/6, partd = dp%6;
        const float* W1 = (dec==0 ? dfw1 : dhw1) + partd*400;
        for (int i = tid; i < 400; i += 384){
            int o = i/20, c = i%20;
            wtd[c*20+o] = W1[i];
        }
        if (tid < 20) { ssum[tid]=0.f; ssq[tid]=0.f; }
        __syncthreads();

        int p = (bi%171)*384 + tid;
        bool valid = p < NPIXs;
        int pc = valid ? p : 0;
        int bb = pc >> 14, pix = pc & (HWs-1);
        const float* a   = (dec==0) ? (xf + bb*HD*HWs)
                                    : (xh + (((partd<4?0:1)*Bn + bb)*HD)*HWs);
        const float* xpi = xp + (partd*Bn+bb)*HD*HWs;

        float in[20];
#pragma unroll
        for (int c=0;c<10;c++) in[c]    = valid ? __ldg(a   + c*HWs + pix) : 0.f;
#pragma unroll
        for (int c=0;c<10;c++) in[10+c] = valid ? __ldg(xpi + c*HWs + pix) : 0.f;

        float out[20];
#pragma unroll
        for (int o=0;o<20;o++) out[o]=0.f;
#pragma unroll
        for (int c=0;c<20;c++){
            float vc = in[c];
            const float4* wp = (const float4*)&wtd[c*20];
#pragma unroll
            for (int j=0;j<5;j++){
                float4 w4 = wp[j];
                out[4*j+0] += vc*w4.x; out[4*j+1] += vc*w4.y;
                out[4*j+2] += vc*w4.z; out[4*j+3] += vc*w4.w;
            }
        }
        for (int o=0;o<20;o++){
            float v = valid ? out[o] : 0.f;
            float v2 = v*v;
            for (int off=16; off; off>>=1){
                v  += __shfl_down_sync(0xffffffffu, v,  off);
                v2 += __shfl_down_sync(0xffffffffu, v2, off);
            }
            if ((tid&31)==0){ atomicAdd(&ssum[o], v); atomicAdd(&ssq[o], v2); }
        }
        __syncthreads();
        if (tid < 20){
            atomicAdd(&g_sum[dp*40 + tid*2],   ssum[tid]);
            atomicAdd(&g_sum[dp*40 + tid*2+1], ssq[tid]);
        }
    }
}

// -------- finalizeA: BN affine for decomp (dec) + deform1 (bn1) -------------
__global__ void finalizeA_kernel(const float* __restrict__ dfg, const float* __restrict__ dfb,
                                 const float* __restrict__ dhg, const float* __restrict__ dhb,
                                 const float* __restrict__ g1,  const float* __restrict__ b1)
{
    int i = threadIdx.x;
    if (i < 240){
        int dp = i/20, ch = i%20, part = dp%6;
        float N = 65536.f;
        float mean = g_sum[dp*40+ch*2] / N;
        float var  = g_sum[dp*40+ch*2+1] / N - mean*mean;
        const float* g = (dp<6 ? dfg : dhg) + part*20;
        const float* b = (dp<6 ? dfb : dhb) + part*20;
        float sc = g[ch] * rsqrtf(var + 1e-5f);
        g_dscale[i] = sc;
        g_dshift[i] = b[ch] - mean*sc;
    }
    if (i < 120){
        int part = i/20, ch = i%20;
        float mean = g_sum[512+part*40+ch*2] / 65536.f;
        float var  = g_sum[512+part*40+ch*2+1] / 65536.f - mean*mean;
        float sc = g1[part*20+ch]*rsqrtf(var + 1e-5f);
        g_scale1[i] = sc;
        g_shift1[i] = b1[part*20+ch] - mean*sc;
    }
}

// ===== fused kernel 2: om2 (blocks x<32) + decomp_out (blocks x>=32) ========
__global__ __launch_bounds__(384) void fused2_kernel(
    const float* __restrict__ offw, const float* __restrict__ offb,
    const float* __restrict__ xf, const float* __restrict__ xh, const float* __restrict__ xp,
    const float* __restrict__ dfw1, const float* __restrict__ dhw1,
    const float* __restrict__ dfw2, const float* __restrict__ dfb2,
    const float* __restrict__ dhw2, const float* __restrict__ dhb2,
    float* __restrict__ out)
{
    __shared__ __align__(16) float tileS[10][18][36];
    __shared__ __align__(16) float wtc[3240];
    __shared__ float ssc[20], ssh[20];
    __shared__ __align__(16) float wtd[400];
    __shared__ float sw[20], scb[20], shb[20];

    int tid = threadIdx.x;
    int part = blockIdx.z, b = blockIdx.y;

    if (blockIdx.x < 32){
        // ---------------- om2: offset conv 2 (20ch -> 27ch) -----------------
        int xblk = blockIdx.x;
        int ty0 = (xblk>>2)*16, tx0 = (xblk&3)*32;
        int og = tid>>7, lt = tid&127;
        int r = lt>>3, x0 = (lt&7)*4;
        if (tid < 20){ ssc[tid] = g_scale1[part*20+tid]; ssh[tid] = g_shift1[part*20+tid]; }

        const float* sp0 = g_y1 + (part*Bn+b)*C2c*HWs;
        const float* W = offw + part*27*C2c*9;

        float acc[9][4];
#pragma unroll
        for (int o=0;o<9;o++)
#pragma unroll
            for (int p=0;p<4;p++) acc[o][p] = 0.f;

        for (int chunk=0; chunk<2; chunk++){
            __syncthreads();
            for (int i=tid; i<2430; i+=384){
                int t = i%9, c = (i/9)%10, o27 = i/90;
                int ogl = o27/9, o = o27%9;
                wtc[(c*9+t)*36 + ogl*12 + o] = W[(o27*C2c + chunk*10 + c)*9 + t];
            }
            for (int i=tid; i<6120; i+=384){
                int c = i/612, rem = i%612, rr = rem/34, cc = rem%34;
                int gy = ty0-1+rr, gx = tx0-1+cc;
                int gc = chunk*10+c;
                float v = 0.f;
                if (gy>=0 && gy<Hh && gx>=0 && gx<Ww){
                    v = sp0[gc*HWs + gy*Ww + gx];
                    v = fmaxf(v*ssc[gc] + ssh[gc], 0.f);
                }
                tileS[c][rr][cc] = v;
            }
            __syncthreads();
#pragma unroll 2
            for (int c=0;c<10;c++){
                float in[3][6];
#pragma unroll
                for (int dy=0;dy<3;dy++){
                    const float* trow = &tileS[c][r+dy][x0];
                    float4 a4 = *(const float4*)trow;
                    float2 b2 = *(const float2*)(trow+4);
                    in[dy][0]=a4.x; in[dy][1]=a4.y; in[dy][2]=a4.z; in[dy][3]=a4.w;
                    in[dy][4]=b2.x; in[dy][5]=b2.y;
                }
#pragma unroll
                for (int t=0;t<9;t++){
                    const float* wp = &wtc[(c*9+t)*36 + og*12];
                    float4 wa = *(const float4*)wp;
                    float4 wb = *(const float4*)(wp+4);
                    float  w8 = wp[8];
                    float iv0 = in[t/3][t%3+0], iv1 = in[t/3][t%3+1];
                    float iv2 = in[t/3][t%3+2], iv3 = in[t/3][t%3+3];
                    acc[0][0]+=iv0*wa.x; acc[0][1]+=iv1*wa.x; acc[0][2]+=iv2*wa.x; acc[0][3]+=iv3*wa.x;
                    acc[1][0]+=iv0*wa.y; acc[1][1]+=iv1*wa.y; acc[1][2]+=iv2*wa.y; acc[1][3]+=iv3*wa.y;
                    acc[2][0]+=iv0*wa.z; acc[2][1]+=iv1*wa.z; acc[2][2]+=iv2*wa.z; acc[2][3]+=iv3*wa.z;
                    acc[3][0]+=iv0*wa.w; acc[3][1]+=iv1*wa.w; acc[3][2]+=iv2*wa.w; acc[3][3]+=iv3*wa.w;
                    acc[4][0]+=iv0*wb.x; acc[4][1]+=iv1*wb.x; acc[4][2]+=iv2*wb.x; acc[4][3]+=iv3*wb.x;
                    acc[5][0]+=iv0*wb.y; acc[5][1]+=iv1*wb.y; acc[5][2]+=iv2*wb.y; acc[5][3]+=iv3*wb.y;
                    acc[6][0]+=iv0*wb.z; acc[6][1]+=iv1*wb.z; acc[6][2]+=iv2*wb.z; acc[6][3]+=iv3*wb.z;
                    acc[7][0]+=iv0*wb.w; acc[7][1]+=iv1*wb.w; acc[7][2]+=iv2*wb.w; acc[7][3]+=iv3*wb.w;
                    acc[8][0]+=iv0*w8;   acc[8][1]+=iv1*w8;   acc[8][2]+=iv2*w8;   acc[8][3]+=iv3*w8;
                }
            }
        }
        float* omp = g_om2 + (part*Bn+b)*27*HWs;
        int y = ty0+r;
#pragma unroll
        for (int o=0;o<9;o++){
            int oo = og*9+o;
            float bv = __ldg(offb + part*27 + oo);
#pragma unroll
            for (int p=0;p<4;p++)
                omp[oo*HWs + y*Ww + tx0+x0+p] = acc[o][p] + bv;
        }
    } else {
        // ---------------- decomp_out: recompute t, BN+leaky+W2+sigmoid ------
        int bi = (blockIdx.x-32) + 86*(blockIdx.z*4 + blockIdx.y);
        if (bi >= 2052) return;
        int dp = bi/171, dec = dp/6, partd = dp%6;
        const float* W1 = (dec==0 ? dfw1 : dhw1) + partd*400;
        for (int i = tid; i < 400; i += 384){
            int o = i/20, c = i%20;
            wtd[c*20+o] = W1[i];
        }
        if (tid < 20){
            sw[tid]  = ((dec==0 ? dfw2 : dhw2) + partd*20)[tid];
            scb[tid] = g_dscale[dp*20+tid];
            shb[tid] = g_dshift[dp*20+tid];
        }
        __syncthreads();

        int p = (bi%171)*384 + tid;
        if (p >= NPIXs) return;
        int bb = p >> 14, pix = p & (HWs-1);
        const float* a   = (dec==0) ? (xf + bb*HD*HWs)
                                    : (xh + (((partd<4?0:1)*Bn + bb)*HD)*HWs);
        const float* xpi = xp + (partd*Bn+bb)*HD*HWs;

        float in[20];
#pragma unroll
        for (int c=0;c<10;c++) in[c]    = __ldg(a   + c*HWs + pix);
#pragma unroll
        for (int c=0;c<10;c++) in[10+c] = __ldg(xpi + c*HWs + pix);

        float out_t[20];
#pragma unroll
        for (int o=0;o<20;o++) out_t[o]=0.f;
#pragma unroll
        for (int c=0;c<20;c++){
            float vc = in[c];
            const float4* wp = (const float4*)&wtd[c*20];
#pragma unroll
            for (int j=0;j<5;j++){
                float4 w4 = wp[j];
                out_t[4*j+0] += vc*w4.x; out_t[4*j+1] += vc*w4.y;
                out_t[4*j+2] += vc*w4.z; out_t[4*j+3] += vc*w4.w;
            }
        }
        float b2 = (dec==0 ? dfb2 : dhb2)[partd];
        float s = b2;
#pragma unroll
        for (int c=0;c<20;c++){
            float t = out_t[c]*scb[c] + shb[c];
            t = (t >= 0.f) ? t : 0.01f*t;
            s += sw[c]*t;
        }
        out[OUT_XP + dec*OUT_A + partd*NPIXs + p] = 1.f/(1.f+__expf(-s));
    }
}

// ------- deform conv 1 (50ch -> 20ch), fp16 tile, 2 px/thread ---------------
__global__ __launch_bounds__(256) void deform1_kernel(
    const float* __restrict__ xf, const float* __restrict__ xh, const float* __restrict__ xp,
    const float* __restrict__ w1)
{
    int part = blockIdx.z, b = blockIdx.y;
    int ty0 = (blockIdx.x>>3)*32, tx0 = (blockIdx.x&7)*16;
    int tid = threadIdx.x;
    int ly = tid>>4, lx = tid&15;
    int sy0 = ty0-3, sx0 = tx0-3;   // halo 38 rows x 22 cols

    __shared__ __align__(16) float wt[1800];        // [(c*9+k)*20+o], 10ch chunk
    __shared__ __align__(16) __half2 tileH[5][836]; // [cpair][pos 38x22]
    __shared__ float ssum[20], ssq[20];

    const float* src0 = xp + (part*Bn+b)*HD*HWs;
    const float* src1 = xf + b*HD*HWs;
    const float* src2 = xh + (((part<4?0:1)*Bn+b)*HD)*HWs;
    const float* src3 = xp + (c_nbr0[part]*Bn+b)*HD*HWs;
    const float* src4 = xp + (c_nbr1[part]*Bn+b)*HD*HWs;
    const float* Wm = w1 + part*9000;
    if (tid < 20){ ssum[tid]=0.f; ssq[tid]=0.f; }

    int pix0 = (ty0+ly)*Ww + tx0+lx;
    int pix1 = pix0 + 16*Ww;

    float tw[2][9][4]; int tiy[2][9], tix[2][9]; unsigned inmask[2] = {0u,0u};
    for (int j=0;j<2;j++){
        int yj = ty0+ly + j*16, xj = tx0+lx;
        const float* omp = g_om1 + (part*Bn+b)*27*HWs + (j ? pix1 : pix0);
        for (int k=0;k<9;k++){
            float dy = omp[(2*k)*HWs], dx = omp[(2*k+1)*HWs];
            float m  = 1.f/(1.f+__expf(-omp[(18+k)*HWs]));
            float py = (float)(yj + k/3 - 1) + dy;
            float px = (float)(xj + (k%3) - 1) + dx;
            float fy = floorf(py), fx = floorf(px);
            float wy = py-fy, wx = px-fx;
            int iy = (int)fy, ix = (int)fx;
            tw[j][k][0] = (1.f-wy)*(1.f-wx)*m;
            tw[j][k][1] = (1.f-wy)*wx*m;
            tw[j][k][2] = wy*(1.f-wx)*m;
            tw[j][k][3] = wy*wx*m;
            tiy[j][k]=iy; tix[j][k]=ix;
            if (iy>=sy0 && iy<=sy0+36 && ix>=sx0 && ix<=sx0+20) inmask[j] |= (1u<<k);
        }
    }
    float acc[2][20];
#pragma unroll
    for (int j=0;j<2;j++)
#pragma unroll
        for (int o=0;o<20;o++) acc[j][o]=0.f;

    for (int chunk=0; chunk<5; chunk++){
        const float* spb;
        switch (chunk){
            case 0: spb = src0; break;
            case 1: spb = src1; break;
            case 2: spb = src2; break;
            case 3: spb = src3; break;
            default: spb = src4; break;
        }
        __syncthreads();
        for (int i=tid; i<1800; i+=256){
            int o = i%20, k = (i/20)%9, c = i/180;
            wt[(c*9+k)*20+o] = Wm[(o*50 + chunk*10 + c)*9 + k];
        }
        for (int i=tid; i<4180; i+=256){
            int p = i/836, rem = i%836;
            int gy = sy0+rem/22, gx = sx0+rem%22;
            float v0 = 0.f, v1 = 0.f;
            if (gy>=0 && gy<Hh && gx>=0 && gx<Ww){
                int gp = gy*Ww+gx;
                v0 = spb[(2*p  )*HWs + gp];
                v1 = spb[(2*p+1)*HWs + gp];
            }
            tileH[p][rem] = __floats2half2_rn(v0, v1);
        }
        __syncthreads();
        for (int k=0;k<9;k++){
            float v[2][10];
#pragma unroll
            for (int j=0;j<2;j++){
                float w00=tw[j][k][0], w01=tw[j][k][1], w10=tw[j][k][2], w11=tw[j][k][3];
                int iy=tiy[j][k], ix=tix[j][k];
                if (inmask[j] & (1u<<k)){
                    int base = (iy-sy0)*22 + (ix-sx0);
#pragma unroll
                    for (int p=0;p<5;p++){
                        const __half2* tp = tileH[p];
                        float2 fa = __half22float2(tp[base]);
                        float2 fb = __half22float2(tp[base+1]);
                        float2 fc = __half22float2(tp[base+22]);
                        float2 fd = __half22float2(tp[base+23]);
                        v[j][2*p+0] = w00*fa.x + w01*fb.x + w10*fc.x + w11*fd.x;
                        v[j][2*p+1] = w00*fa.y + w01*fb.y + w10*fc.y + w11*fd.y;
                    }
                } else {
                    bool vy0 = (iy>=0)&&(iy<Hh),   vy1 = (iy+1>=0)&&(iy+1<Hh);
                    bool vx0 = (ix>=0)&&(ix<Ww),   vx1 = (ix+1>=0)&&(ix+1<Ww);
                    int i00 = iy*Ww+ix;
#pragma unroll
                    for (int c=0;c<10;c++){
                        const float* sp = spb + c*HWs;
                        float v00 = (vy0&&vx0)? sp[i00]      : 0.f;
                        float v01 = (vy0&&vx1)? sp[i00+1]    : 0.f;
                        float v10 = (vy1&&vx0)? sp[i00+Ww]   : 0.f;
                        float v11 = (vy1&&vx1)? sp[i00+Ww+1] : 0.f;
                        v[j][c] = w00*v00 + w01*v01 + w10*v10 + w11*v11;
                    }
                }
            }
#pragma unroll
            for (int c=0;c<10;c++){
                float v0 = v[0][c], v1 = v[1][c];
                const float4* wp = (const float4*)&wt[(c*9+k)*20];
#pragma unroll
                for (int q=0;q<5;q++){
                    float4 w4 = wp[q];
                    acc[0][4*q+0] += v0*w4.x; acc[0][4*q+1] += v0*w4.y;
                    acc[0][4*q+2] += v0*w4.z; acc[0][4*q+3] += v0*w4.w;
                    acc[1][4*q+0] += v1*w4.x; acc[1][4*q+1] += v1*w4.y;
                    acc[1][4*q+2] += v1*w4.z; acc[1][4*q+3] += v1*w4.w;
                }
            }
        }
    }
    float* yb = g_y1 + (part*Bn+b)*C2c*HWs;
#pragma unroll
    for (int o=0;o<20;o++){
        yb[o*HWs + pix0] = acc[0][o];
        yb[o*HWs + pix1] = acc[1][o];
    }
    for (int o=0;o<20;o++){
        float v  = acc[0][o]+acc[1][o];
        float v2 = acc[0][o]*acc[0][o]+acc[1][o]*acc[1][o];
        for (int off=16; off; off>>=1){
            v  += __shfl_down_sync(0xffffffffu, v,  off);
            v2 += __shfl_down_sync(0xffffffffu, v2, off);
        }
        if ((tid&31)==0){ atomicAdd(&ssum[o], v); atomicAdd(&ssq[o], v2); }
    }
    __syncthreads();
    if (tid < 20){
        atomicAdd(&g_sum[512 + part*40 + tid*2],   ssum[tid]);
        atomicAdd(&g_sum[512 + part*40 + tid*2+1], ssq[tid]);
    }
}

// ------- deform conv 2 (20ch -> 10ch), fp16 tile, 2 px/thread ---------------
__global__ __launch_bounds__(256) void deform2_kernel(const float* __restrict__ w2)
{
    int part = blockIdx.z, b = blockIdx.y;
    int ty0 = (blockIdx.x>>3)*32, tx0 = (blockIdx.x&7)*16;
    int tid = threadIdx.x;
    int ly = tid>>4, lx = tid&15;
    int sy0 = ty0-3, sx0 = tx0-3;

    __shared__ __align__(16) float wt[1080];        // [(c*9+k)*12+o], 10ch chunk
    __shared__ __align__(16) __half2 tileH[5][836];
    __shared__ float ssc[20], ssh[20];
    __shared__ float ssum[10], ssq[10];

    const float* t1p = g_y1 + (part*Bn+b)*C2c*HWs;
    const float* Wm = w2 + part*1800;
    if (tid < 20){ ssc[tid] = g_scale1[part*20+tid]; ssh[tid] = g_shift1[part*20+tid]; }
    if (tid < 10){ ssum[tid]=0.f; ssq[tid]=0.f; }
    __syncthreads();

    int pix0 = (ty0+ly)*Ww + tx0+lx;
    int pix1 = pix0 + 16*Ww;

    float tw[2][9][4]; int tiy[2][9], tix[2][9]; unsigned inmask[2] = {0u,0u};
    for (int j=0;j<2;j++){
        int yj = ty0+ly + j*16, xj = tx0+lx;
        const float* omp = g_om2 + (part*Bn+b)*27*HWs + (j ? pix1 : pix0);
        for (int k=0;k<9;k++){
            float dy = omp[(2*k)*HWs], dx = omp[(2*k+1)*HWs];
            float m  = 1.f/(1.f+__expf(-omp[(18+k)*HWs]));
            float py = (float)(yj + k/3 - 1) + dy;
            float px = (float)(xj + (k%3) - 1) + dx;
            float fy = floorf(py), fx = floorf(px);
            float wy = py-fy, wx = px-fx;
            int iy = (int)fy, ix = (int)fx;
            tw[j][k][0] = (1.f-wy)*(1.f-wx)*m;
            tw[j][k][1] = (1.f-wy)*wx*m;
            tw[j][k][2] = wy*(1.f-wx)*m;
            tw[j][k][3] = wy*wx*m;
            tiy[j][k]=iy; tix[j][k]=ix;
            if (iy>=sy0 && iy<=sy0+36 && ix>=sx0 && ix<=sx0+20) inmask[j] |= (1u<<k);
        }
    }
    float acc[2][10];
#pragma unroll
    for (int j=0;j<2;j++)
#pragma unroll
        for (int o=0;o<10;o++) acc[j][o]=0.f;

    for (int chunk=0; chunk<2; chunk++){
        __syncthreads();
        for (int i=tid; i<900; i+=256){
            int o = i%10, k = (i/10)%9, c = i/90;
            wt[(c*9+k)*12+o] = Wm[(o*20 + chunk*10 + c)*9 + k];
        }
        for (int i=tid; i<4180; i+=256){
            int p = i/836, rem = i%836;
            int gy = sy0+rem/22, gx = sx0+rem%22;
            float v0 = 0.f, v1 = 0.f;
            if (gy>=0 && gy<Hh && gx>=0 && gx<Ww){
                int gp = gy*Ww+gx;
                int gc0 = chunk*10 + 2*p;
                v0 = fmaxf(t1p[gc0*HWs + gp]*ssc[gc0] + ssh[gc0], 0.f);
                v1 = fmaxf(t1p[(gc0+1)*HWs + gp]*ssc[gc0+1] + ssh[gc0+1], 0.f);
            }
            tileH[p][rem] = __floats2half2_rn(v0, v1);
        }
        __syncthreads();
        for (int k=0;k<9;k++){
            float v[2][10];
#pragma unroll
            for (int j=0;j<2;j++){
                float w00=tw[j][k][0], w01=tw[j][k][1], w10=tw[j][k][2], w11=tw[j][k][3];
                int iy=tiy[j][k], ix=tix[j][k];
                if (inmask[j] & (1u<<k)){
                    int base = (iy-sy0)*22 + (ix-sx0);
#pragma unroll
                    for (int p=0;p<5;p++){
                        const __half2* tp = tileH[p];
                        float2 fa = __half22float2(tp[base]);
                        float2 fb = __half22float2(tp[base+1]);
                        float2 fc = __half22float2(tp[base+22]);
                        float2 fd = __half22float2(tp[base+23]);
                        v[j][2*p+0] = w00*fa.x + w01*fb.x + w10*fc.x + w11*fd.x;
                        v[j][2*p+1] = w00*fa.y + w01*fb.y + w10*fc.y + w11*fd.y;
                    }
                } else {
                    bool vy0 = (iy>=0)&&(iy<Hh),   vy1 = (iy+1>=0)&&(iy+1<Hh);
                    bool vx0 = (ix>=0)&&(ix<Ww),   vx1 = (ix+1>=0)&&(ix+1<Ww);
                    int i00 = iy*Ww+ix;
#pragma unroll
                    for (int c=0;c<10;c++){
                        int gc = chunk*10+c;
                        const float* sp = t1p + gc*HWs;
                        float sc2 = ssc[gc], sh2 = ssh[gc];
                        float v00 = (vy0&&vx0)? fmaxf(sp[i00]     *sc2+sh2,0.f) : 0.f;
                        float v01 = (vy0&&vx1)? fmaxf(sp[i00+1]   *sc2+sh2,0.f) : 0.f;
                        float v10 = (vy1&&vx0)? fmaxf(sp[i00+Ww]  *sc2+sh2,0.f) : 0.f;
                        float v11 = (vy1&&vx1)? fmaxf(sp[i00+Ww+1]*sc2+sh2,0.f) : 0.f;
                        v[j][c] = w00*v00 + w01*v01 + w10*v10 + w11*v11;
                    }
                }
            }
#pragma unroll
            for (int c=0;c<10;c++){
                float v0 = v[0][c], v1 = v[1][c];
                const float* wp = &wt[(c*9+k)*12];
                float4 wa = *(const float4*)wp;
                float4 wb = *(const float4*)(wp+4);
                float2 wc = *(const float2*)(wp+8);
                acc[0][0]+=v0*wa.x; acc[0][1]+=v0*wa.y; acc[0][2]+=v0*wa.z; acc[0][3]+=v0*wa.w;
                acc[0][4]+=v0*wb.x; acc[0][5]+=v0*wb.y; acc[0][6]+=v0*wb.z; acc[0][7]+=v0*wb.w;
                acc[0][8]+=v0*wc.x; acc[0][9]+=v0*wc.y;
                acc[1][0]+=v1*wa.x; acc[1][1]+=v1*wa.y; acc[1][2]+=v1*wa.z; acc[1][3]+=v1*wa.w;
                acc[1][4]+=v1*wb.x; acc[1][5]+=v1*wb.y; acc[1][6]+=v1*wb.z; acc[1][7]+=v1*wb.w;
                acc[1][8]+=v1*wc.x; acc[1][9]+=v1*wc.y;
            }
        }
    }
    float* yb = g_y2 + (part*Bn+b)*HD*HWs;
#pragma unroll
    for (int o=0;o<10;o++){
        yb[o*HWs + pix0] = acc[0][o];
        yb[o*HWs + pix1] = acc[1][o];
    }
    for (int o=0;o<10;o++){
        float v  = acc[0][o]+acc[1][o];
        float v2 = acc[0][o]*acc[0][o]+acc[1][o]*acc[1][o];
        for (int off=16; off; off>>=1){
            v  += __shfl_down_sync(0xffffffffu, v,  off);
            v2 += __shfl_down_sync(0xffffffffu, v2, off);
        }
        if ((tid&31)==0){ atomicAdd(&ssum[o], v); atomicAdd(&ssq[o], v2); }
    }
    __syncthreads();
    if (tid < 10){
        atomicAdd(&g_sum[1024 + part*20 + tid*2],   ssum[tid]);
        atomicAdd(&g_sum[1024 + part*20 + tid*2+1], ssq[tid]);
    }
}

__global__ void finalize2_kernel(const float* __restrict__ g2, const float* __restrict__ b2){
    int i = threadIdx.x;
    if (i < 60){
        int part = i/10, ch = i%10;
        float mean = g_sum[1024+part*20+ch*2] / 65536.f;
        float var  = g_sum[1024+part*20+ch*2+1] / 65536.f - mean*mean;
        float sc = g2[part*10+ch]*rsqrtf(var + 1e-5f);
        g_scale2[i] = sc;
        g_shift2[i] = b2[part*10+ch] - mean*sc;
    }
}

__global__ void final_kernel(const float* __restrict__ xp, const float* __restrict__ gamma,
                             float* __restrict__ out)
{
    int idx4 = blockIdx.x*256 + threadIdx.x;
    if (idx4 >= OUT_XP/4) return;
    int idx = idx4*4;
    int ch = (idx >> 14) % HD;
    int part = idx / (Bn*HD*HWs);
    float sc = g_scale2[part*HD+ch], sh = g_shift2[part*HD+ch];
    float gm = __ldg(gamma + part);
    float4 yv = *(const float4*)&g_y2[idx];
    float4 xv = *(const float4*)&xp[idx];
    float4 r;
    r.x = fmaxf(gm*xv.x + fmaxf(yv.x*sc+sh, 0.f), 0.f);
    r.y = fmaxf(gm*xv.y + fmaxf(yv.y*sc+sh, 0.f), 0.f);
    r.z = fmaxf(gm*xv.z + fmaxf(yv.z*sc+sh, 0.f), 0.f);
    r.w = fmaxf(gm*xv.w + fmaxf(yv.w*sc+sh, 0.f), 0.f);
    *(float4*)&out[idx] = r;
}

// ---------------------------------------------------------------------------
extern "C" void kernel_launch(void* const* d_in, const int* in_sizes, int n_in,
                              void* d_out, int out_size)
{
    const float* xf   = (const float*)d_in[0];
    const float* xh   = (const float*)d_in[1];
    const float* xp   = (const float*)d_in[2];
    const float* dfw1 = (const float*)d_in[3];
    const float* dfg1 = (const float*)d_in[4];
    const float* dfb1 = (const float*)d_in[5];
    const float* dfw2 = (const float*)d_in[6];
    const float* dfb2 = (const float*)d_in[7];
    const float* dhw1 = (const float*)d_in[8];
    const float* dhg1 = (const float*)d_in[9];
    const float* dhb1 = (const float*)d_in[10];
    const float* dhw2 = (const float*)d_in[11];
    const float* dhb2 = (const float*)d_in[12];
    const float* off1w= (const float*)d_in[13];
    const float* off1b= (const float*)d_in[14];
    const float* w1   = (const float*)d_in[15];
    const float* g1   = (const float*)d_in[16];
    const float* b1   = (const float*)d_in[17];
    const float* off2w= (const float*)d_in[18];
    const float* off2b= (const float*)d_in[19];
    const float* w2   = (const float*)d_in[20];
    const float* g2   = (const float*)d_in[21];
    const float* b2   = (const float*)d_in[22];
    const float* gamma= (const float*)d_in[23];
    float* out = (float*)d_out;

    zero_sums_kernel<<<6, 256>>>();
    fused1_kernel<<<dim3(118,4,6), 384>>>(xf, xh, xp, off1w, off1b, dfw1, dhw1);
    deform1_kernel<<<dim3(32,4,6), 256>>>(xf, xh, xp, w1);
    finalizeA_kernel<<<1, 256>>>(dfg1, dfb1, dhg1, dhb1, g1, b1);
    fused2_kernel<<<dim3(118,4,6), 384>>>(off2w, off2b, xf, xh, xp, dfw1, dhw1,
                                          dfw2, dfb2, dhw2, dhb2, out);
    deform2_kernel<<<dim3(32,4,6), 256>>>(w2);
    finalize2_kernel<<<1, 64>>>(g2, b2);
    final_kernel<<<(OUT_XP/4+255)/256, 256>>>(xp, gamma, out);
}